// round 16
// baseline (speedup 1.0000x reference)
#include <cuda_runtime.h>
#include <cuda_bf16.h>
#include <cuda_fp16.h>
#include <cstdint>

// ---------------- problem constants ------------------------------------------
#define NMAX   100000
#define EMAX   1600000
#define DIN    128
#define DH     128
#define DOUT   64
#define NREL   3
#define NPAIR  6
#define SCAN_CHUNK 1024
#define MAXBLK 128

// ---------------- scratch (__device__ globals; no allocation allowed) --------
__device__ __align__(128) __half g_z3[(size_t)NMAX * (NREL * DIN)];
__device__ __align__(128) __nv_bfloat16 g_ahi[(size_t)NMAX * DIN];
__device__ __align__(128) __nv_bfloat16 g_alo[(size_t)NMAX * DIN];
__device__ __align__(128) __nv_bfloat16 g_w1hi[NREL * DIN * DH], g_w1lo[NREL * DIN * DH];
__device__ __align__(128) __nv_bfloat16 g_w2hi[NREL * DH * DOUT], g_w2lo[NREL * DH * DOUT];
__device__ int   g_degi[12 * NMAX];
__device__ float g_degf[12 * NMAX];
__device__ int   g_off [NPAIR * NMAX];
__device__ int   g_cnt [NPAIR * NMAX];
__device__ int   g_adj [(size_t)NPAIR * EMAX];
__device__ int   g_bsum[NPAIR * MAXBLK];

// ---------------- cp.async / mma helpers --------------------------------------
__device__ __forceinline__ void cpa16(void* smem, const void* g, bool valid) {
    uint32_t s = (uint32_t)__cvta_generic_to_shared(smem);
    int sz = valid ? 16 : 0;
    asm volatile("cp.async.cg.shared.global [%0], [%1], 16, %2;\n"
                 :: "r"(s), "l"(g), "r"(sz));
}
__device__ __forceinline__ void cpa_commit() {
    asm volatile("cp.async.commit_group;\n" ::: "memory");
}
__device__ __forceinline__ void cpa_wait0() {
    asm volatile("cp.async.wait_group 0;\n" ::: "memory");
}
__device__ __forceinline__ void ldsm_x4(uint32_t* r, uint32_t addr) {
    asm volatile("ldmatrix.sync.aligned.m8n8.x4.shared.b16 {%0,%1,%2,%3}, [%4];"
                 : "=r"(r[0]), "=r"(r[1]), "=r"(r[2]), "=r"(r[3]) : "r"(addr));
}
__device__ __forceinline__ void ldsm_x4t(uint32_t* r, uint32_t addr) {
    asm volatile("ldmatrix.sync.aligned.m8n8.x4.trans.shared.b16 {%0,%1,%2,%3}, [%4];"
                 : "=r"(r[0]), "=r"(r[1]), "=r"(r[2]), "=r"(r[3]) : "r"(addr));
}
__device__ __forceinline__ void mma16816(float* d, const uint32_t* a, const uint32_t* b) {
    asm volatile("mma.sync.aligned.m16n8k16.row.col.f32.bf16.bf16.f32 "
                 "{%0,%1,%2,%3},{%4,%5,%6,%7},{%8,%9},{%0,%1,%2,%3};"
                 : "+f"(d[0]), "+f"(d[1]), "+f"(d[2]), "+f"(d[3])
                 : "r"(a[0]), "r"(a[1]), "r"(a[2]), "r"(a[3]), "r"(b[0]), "r"(b[1]));
}

// ---------------- fp32 -> (bf16 hi, bf16 lo) split ---------------------------
__global__ void split_kernel(const float* __restrict__ src,
                             __nv_bfloat16* __restrict__ hi,
                             __nv_bfloat16* __restrict__ lo, int n) {
    int i = blockIdx.x * blockDim.x + threadIdx.x;
    if (i >= n) return;
    float v = __ldg(src + i);
    __nv_bfloat16 h = __float2bfloat16(v);
    hi[i] = h;
    lo[i] = __float2bfloat16(v - __bfloat162float(h));
}

// ---------------- degree counting ---------------------------------------------
__global__ void count_deg_kernel(const int* __restrict__ ei, int* __restrict__ degi,
                                 int E, int M, int pbase) {
    int p = pbase + blockIdx.y;
    int e = blockIdx.x * blockDim.x + threadIdx.x;
    if (e >= E) return;
    int s = __ldg(ei + (size_t)(p * 2 + 0) * E + e);
    int d = __ldg(ei + (size_t)(p * 2 + 1) * E + e);
    atomicAdd(degi + (size_t)(p * 2 + 0) * M + s, 1);
    atomicAdd(degi + (size_t)(p * 2 + 1) * M + d, 1);
}

__global__ void rsqrt_kernel(const int* __restrict__ degi, float* __restrict__ degf, int n) {
    int i = blockIdx.x * blockDim.x + threadIdx.x;
    if (i < n) degf[i] = rsqrtf((float)max(degi[i], 1));
}

// ---------------- exclusive scan -> CSR offsets -------------------------------
__global__ __launch_bounds__(256)
void scanA(const int* __restrict__ degi, int* __restrict__ off,
           int* __restrict__ bsum, int M, int pbase) {
    int p = pbase + blockIdx.y;
    const int* deg = degi + (size_t)(p * 2 + 1) * M;
    int* o = off + (size_t)p * M;
    int base = blockIdx.x * SCAN_CHUNK;
    int tid = threadIdx.x;

    int v[4];
    int t = 0;
    #pragma unroll
    for (int k = 0; k < 4; k++) {
        int idx = base + tid * 4 + k;
        v[k] = (idx < M) ? deg[idx] : 0;
        t += v[k];
    }
    __shared__ int sm[256];
    sm[tid] = t;
    __syncthreads();
    #pragma unroll
    for (int ofs = 1; ofs < 256; ofs <<= 1) {
        int u = (tid >= ofs) ? sm[tid - ofs] : 0;
        __syncthreads();
        sm[tid] += u;
        __syncthreads();
    }
    int run = sm[tid] - t;
    #pragma unroll
    for (int k = 0; k < 4; k++) {
        int idx = base + tid * 4 + k;
        if (idx < M) o[idx] = run;
        run += v[k];
    }
    if (tid == 255) bsum[p * MAXBLK + blockIdx.x] = sm[255];
}

__global__ __launch_bounds__(MAXBLK)
void scanB(int* __restrict__ bsum, int nblk, int pbase) {
    int p = pbase + blockIdx.x;
    int tid = threadIdx.x;
    int* b = bsum + p * MAXBLK;
    int t = (tid < nblk) ? b[tid] : 0;
    __shared__ int sm[MAXBLK];
    sm[tid] = t;
    __syncthreads();
    #pragma unroll
    for (int ofs = 1; ofs < MAXBLK; ofs <<= 1) {
        int u = (tid >= ofs) ? sm[tid - ofs] : 0;
        __syncthreads();
        sm[tid] += u;
        __syncthreads();
    }
    if (tid < nblk) b[tid] = sm[tid] - t;
}

__global__ void scanC(int* __restrict__ off, int* __restrict__ cnt,
                      const int* __restrict__ bsum, int M, int pbase) {
    int p = pbase + blockIdx.y;
    int i = blockIdx.x * blockDim.x + threadIdx.x;
    if (i < M) {
        int v = off[(size_t)p * M + i] + bsum[p * MAXBLK + (i >> 10)];
        off[(size_t)p * M + i] = v;
        cnt[(size_t)p * M + i] = v;
    }
}

__global__ void fill_adj_kernel(const int* __restrict__ ei,
                                int* __restrict__ cnt, int* __restrict__ adj,
                                int E, int M, int pbase) {
    int p = pbase + blockIdx.y;
    int e = blockIdx.x * blockDim.x + threadIdx.x;
    if (e >= E) return;
    int s = __ldg(ei + (size_t)(p * 2 + 0) * E + e);
    int d = __ldg(ei + (size_t)(p * 2 + 1) * E + e);
    int pos = atomicAdd(cnt + (size_t)p * M + d, 1);
    adj[(size_t)p * E + pos] = s;
}

// ---------------- relation-fused mma.sync GEMM, register epilogue -------------
#define A_ST 136

template<int BN, bool SCALE>
__global__ __launch_bounds__(256, 2)
void gemm_fused(const __nv_bfloat16* __restrict__ Ahi,
                const __nv_bfloat16* __restrict__ Alo,
                const __nv_bfloat16* __restrict__ Bhi,
                const __nv_bfloat16* __restrict__ Blo,
                const float* __restrict__ rsbase,
                __half* __restrict__ C, int M) {
    constexpr int LDC = NREL * BN;
    constexpr int BST = BN + 8;
    constexpr int KCH = 4;
    constexpr int TOT = NREL * KCH;
    constexpr int BXF = 32 * BN / 8;
    constexpr int WNT = BN / 2 / 8;

    extern __shared__ __align__(16) char dsm[];
    __nv_bfloat16* sAhi = reinterpret_cast<__nv_bfloat16*>(dsm);
    __nv_bfloat16* sAlo = sAhi + 128 * A_ST;
    __nv_bfloat16* sB   = sAlo + 128 * A_ST;

    const int tid  = threadIdx.x;
    const int w    = tid >> 5;
    const int lane = tid & 31;
    const int warp_row = w & 3;
    const int warp_col = w >> 2;
    const int m_off = warp_row * 32;
    const int n_off = warp_col * (BN / 2);
    const int row0 = blockIdx.x * 128;

    const uint32_t saHi = (uint32_t)__cvta_generic_to_shared(sAhi);
    const uint32_t saLo = (uint32_t)__cvta_generic_to_shared(sAlo);
    const uint32_t sb0  = (uint32_t)__cvta_generic_to_shared(sB);

    #pragma unroll
    for (int i = 0; i < 8; i++) {
        int slot = tid + i * 256;
        int r = slot >> 4;
        int c = (slot & 15) * 8;
        int gr = row0 + r;
        bool valid = gr < M;
        const __nv_bfloat16* gh = Ahi + (size_t)gr * 128 + c;
        const __nv_bfloat16* gl = Alo + (size_t)gr * 128 + c;
        cpa16(sAhi + r * A_ST + c, valid ? gh : (const void*)Ahi, valid);
        cpa16(sAlo + r * A_ST + c, valid ? gl : (const void*)Alo, valid);
    }

    auto loadB = [&](int it, int st) {
        int rel = it / KCH;
        int kc = (it % KCH) * 32;
        __nv_bfloat16* dh = sB + st * 2 * 32 * BST;
        __nv_bfloat16* dl = dh + 32 * BST;
        const __nv_bfloat16* gh = Bhi + (size_t)rel * 128 * BN;
        const __nv_bfloat16* gl = Blo + (size_t)rel * 128 * BN;
        #pragma unroll
        for (int i = 0; i < BXF / 256; i++) {
            int slot = tid + i * 256;
            int r = slot / (BN / 8);
            int c = (slot % (BN / 8)) * 8;
            cpa16(dh + r * BST + c, gh + (size_t)(kc + r) * BN + c, true);
            cpa16(dl + r * BST + c, gl + (size_t)(kc + r) * BN + c, true);
        }
    };
    loadB(0, 0);
    cpa_commit();

    float acc[2][WNT][4];
    #pragma unroll
    for (int mt = 0; mt < 2; mt++)
        #pragma unroll
        for (int nt = 0; nt < WNT; nt++)
            #pragma unroll
            for (int k = 0; k < 4; k++) acc[mt][nt][k] = 0.0f;

    const int aRow = (lane & 15);
    const int aCol = (lane >> 4) * 8;
    const int bRow = (lane & 7) + ((lane >> 3) & 1) * 8;
    const int bCol = (lane >> 4) * 8;

    for (int it = 0; it < TOT; it++) {
        cpa_wait0();
        __syncthreads();
        if (it + 1 < TOT) { loadB(it + 1, (it + 1) & 1); cpa_commit(); }

        const uint32_t sbh = sb0 + (uint32_t)((it & 1) * 2 * 32 * BST) * 2;
        const uint32_t sbl = sbh + 32 * BST * 2;
        const int kc = (it % KCH) * 32;

        #pragma unroll
        for (int ks = 0; ks < 32; ks += 16) {
            const int kpos = kc + ks;
            uint32_t bhi[WNT][2], blo[WNT][2];
            #pragma unroll
            for (int g = 0; g < WNT / 2; g++) {
                uint32_t t[4];
                uint32_t boff = (uint32_t)((ks + bRow) * BST + n_off + g * 16 + bCol) * 2;
                ldsm_x4t(t, sbh + boff);
                bhi[2 * g][0] = t[0]; bhi[2 * g][1] = t[1];
                bhi[2 * g + 1][0] = t[2]; bhi[2 * g + 1][1] = t[3];
                ldsm_x4t(t, sbl + boff);
                blo[2 * g][0] = t[0]; blo[2 * g][1] = t[1];
                blo[2 * g + 1][0] = t[2]; blo[2 * g + 1][1] = t[3];
            }
            #pragma unroll
            for (int mt = 0; mt < 2; mt++) {
                uint32_t ahi[4], alo[4];
                uint32_t aoff = (uint32_t)((m_off + mt * 16 + aRow) * A_ST + kpos + aCol) * 2;
                ldsm_x4(ahi, saHi + aoff);
                ldsm_x4(alo, saLo + aoff);
                #pragma unroll
                for (int nt = 0; nt < WNT; nt++) {
                    mma16816(acc[mt][nt], ahi, bhi[nt]);
                    mma16816(acc[mt][nt], ahi, blo[nt]);
                    mma16816(acc[mt][nt], alo, bhi[nt]);
                }
            }
        }

        if ((it % KCH) == KCH - 1) {
            int rel = it / KCH;
            const float* rs = rsbase + (size_t)rel * 2 * M;
            #pragma unroll
            for (int mt = 0; mt < 2; mt++) {
                int r0 = row0 + m_off + mt * 16 + (lane >> 2);
                int r1 = r0 + 8;
                float s0 = 1.0f, s1 = 1.0f;
                if (SCALE) {
                    if (r0 < M) s0 = __ldg(rs + r0);
                    if (r1 < M) s1 = __ldg(rs + r1);
                }
                #pragma unroll
                for (int nt = 0; nt < WNT; nt++) {
                    int c = rel * BN + n_off + nt * 8 + (lane & 3) * 2;
                    if (r0 < M) {
                        __half2 p = __floats2half2_rn(acc[mt][nt][0] * s0, acc[mt][nt][1] * s0);
                        *reinterpret_cast<uint32_t*>(C + (size_t)r0 * LDC + c) =
                            *reinterpret_cast<uint32_t*>(&p);
                    }
                    if (r1 < M) {
                        __half2 p = __floats2half2_rn(acc[mt][nt][2] * s1, acc[mt][nt][3] * s1);
                        *reinterpret_cast<uint32_t*>(C + (size_t)r1 * LDC + c) =
                            *reinterpret_cast<uint32_t*>(&p);
                    }
                    #pragma unroll
                    for (int k = 0; k < 4; k++) acc[mt][nt][k] = 0.0f;
                }
            }
        }
    }
}

// ---------------- fused 3-relation gathers (shuffle-batched indices) -----------
__global__ __launch_bounds__(256)
void gatherL1(const __half* __restrict__ z3,
              __nv_bfloat16* __restrict__ ahi, __nv_bfloat16* __restrict__ alo,
              const int* __restrict__ off, const int* __restrict__ degi,
              const int* __restrict__ adj, const float* __restrict__ degf,
              const float* __restrict__ b1, int M, int E) {
    int w = (blockIdx.x * blockDim.x + threadIdx.x) >> 5;
    if (w >= M) return;
    int lane = threadIdx.x & 31;
    float4 tot = make_float4(0.f, 0.f, 0.f, 0.f);

    #pragma unroll
    for (int r = 0; r < NREL; r++) {
        const int*   offp  = off  + (size_t)r * M;
        const int*   degp  = degi + (size_t)(r * 2 + 1) * M;
        const int*   adjp  = adj  + (size_t)r * E;
        const float* rsout = degf + (size_t)(r * 2 + 0) * M;
        const float* rsin  = degf + (size_t)(r * 2 + 1) * M;
        int st = __ldg(offp + w);
        int len = __ldg(degp + w);
        float4 acc = make_float4(0.f, 0.f, 0.f, 0.f);
        const __half* zr = z3 + (size_t)r * 128;

        for (int base = 0; base < len; base += 32) {
            int cnt = min(32, len - base);
            // cooperative: 32 indices via one coalesced load, 32 parallel scale loads
            int   myIdx = 0;
            float myRs  = 0.f;
            if (lane < cnt) {
                myIdx = __ldg(adjp + st + base + lane);
                myRs  = __ldg(rsout + myIdx);
            }
            int j = 0;
            for (; j + 4 <= cnt; j += 4) {
                int   s0 = __shfl_sync(0xffffffffu, myIdx, j + 0);
                int   s1 = __shfl_sync(0xffffffffu, myIdx, j + 1);
                int   s2 = __shfl_sync(0xffffffffu, myIdx, j + 2);
                int   s3 = __shfl_sync(0xffffffffu, myIdx, j + 3);
                float c0 = __shfl_sync(0xffffffffu, myRs, j + 0);
                float c1 = __shfl_sync(0xffffffffu, myRs, j + 1);
                float c2 = __shfl_sync(0xffffffffu, myRs, j + 2);
                float c3 = __shfl_sync(0xffffffffu, myRs, j + 3);
                uint2 q0 = __ldg(reinterpret_cast<const uint2*>(zr + (size_t)s0 * 384 + lane * 4));
                uint2 q1 = __ldg(reinterpret_cast<const uint2*>(zr + (size_t)s1 * 384 + lane * 4));
                uint2 q2 = __ldg(reinterpret_cast<const uint2*>(zr + (size_t)s2 * 384 + lane * 4));
                uint2 q3 = __ldg(reinterpret_cast<const uint2*>(zr + (size_t)s3 * 384 + lane * 4));
                float2 a0 = __half22float2(*reinterpret_cast<__half2*>(&q0.x));
                float2 b0 = __half22float2(*reinterpret_cast<__half2*>(&q0.y));
                float2 a1 = __half22float2(*reinterpret_cast<__half2*>(&q1.x));
                float2 b1v = __half22float2(*reinterpret_cast<__half2*>(&q1.y));
                float2 a2 = __half22float2(*reinterpret_cast<__half2*>(&q2.x));
                float2 b2v = __half22float2(*reinterpret_cast<__half2*>(&q2.y));
                float2 a3 = __half22float2(*reinterpret_cast<__half2*>(&q3.x));
                float2 b3v = __half22float2(*reinterpret_cast<__half2*>(&q3.y));
                acc.x += c0 * a0.x + c1 * a1.x + c2 * a2.x + c3 * a3.x;
                acc.y += c0 * a0.y + c1 * a1.y + c2 * a2.y + c3 * a3.y;
                acc.z += c0 * b0.x + c1 * b1v.x + c2 * b2v.x + c3 * b3v.x;
                acc.w += c0 * b0.y + c1 * b1v.y + c2 * b2v.y + c3 * b3v.y;
            }
            for (; j < cnt; j++) {
                int   s0 = __shfl_sync(0xffffffffu, myIdx, j);
                float c0 = __shfl_sync(0xffffffffu, myRs, j);
                uint2 q0 = __ldg(reinterpret_cast<const uint2*>(zr + (size_t)s0 * 384 + lane * 4));
                float2 a0 = __half22float2(*reinterpret_cast<__half2*>(&q0.x));
                float2 b0 = __half22float2(*reinterpret_cast<__half2*>(&q0.y));
                acc.x += c0 * a0.x; acc.y += c0 * a0.y;
                acc.z += c0 * b0.x; acc.w += c0 * b0.y;
            }
        }
        float ci = __ldg(rsin + w);
        tot.x += ci * acc.x; tot.y += ci * acc.y;
        tot.z += ci * acc.z; tot.w += ci * acc.w;
    }

    int col = lane * 4;
    tot.x = fmaxf(tot.x + __ldg(b1 + col + 0) + __ldg(b1 + 128 + col + 0) + __ldg(b1 + 256 + col + 0), 0.f);
    tot.y = fmaxf(tot.y + __ldg(b1 + col + 1) + __ldg(b1 + 128 + col + 1) + __ldg(b1 + 256 + col + 1), 0.f);
    tot.z = fmaxf(tot.z + __ldg(b1 + col + 2) + __ldg(b1 + 128 + col + 2) + __ldg(b1 + 256 + col + 2), 0.f);
    tot.w = fmaxf(tot.w + __ldg(b1 + col + 3) + __ldg(b1 + 128 + col + 3) + __ldg(b1 + 256 + col + 3), 0.f);

    __nv_bfloat16 hx = __float2bfloat16(tot.x), hy = __float2bfloat16(tot.y);
    __nv_bfloat16 hz = __float2bfloat16(tot.z), hw = __float2bfloat16(tot.w);
    __nv_bfloat16 lx = __float2bfloat16(tot.x - __bfloat162float(hx));
    __nv_bfloat16 ly = __float2bfloat16(tot.y - __bfloat162float(hy));
    __nv_bfloat16 lz = __float2bfloat16(tot.z - __bfloat162float(hz));
    __nv_bfloat16 lw = __float2bfloat16(tot.w - __bfloat162float(hw));
    __nv_bfloat162 h0 = __nv_bfloat162(hx, hy), h1 = __nv_bfloat162(hz, hw);
    __nv_bfloat162 l0 = __nv_bfloat162(lx, ly), l1 = __nv_bfloat162(lz, lw);
    uint2 oh, ol;
    oh.x = *reinterpret_cast<uint32_t*>(&h0); oh.y = *reinterpret_cast<uint32_t*>(&h1);
    ol.x = *reinterpret_cast<uint32_t*>(&l0); ol.y = *reinterpret_cast<uint32_t*>(&l1);
    *reinterpret_cast<uint2*>(ahi + (size_t)w * 128 + col) = oh;
    *reinterpret_cast<uint2*>(alo + (size_t)w * 128 + col) = ol;
}

__global__ __launch_bounds__(256)
void gatherL2(const __half* __restrict__ z3, float* __restrict__ out,
              const int* __restrict__ off, const int* __restrict__ degi,
              const int* __restrict__ adj, const float* __restrict__ degf,
              const float* __restrict__ b2, int M, int E) {
    int w = (blockIdx.x * blockDim.x + threadIdx.x) >> 5;
    if (w >= M) return;
    int lane = threadIdx.x & 31;
    float2 tot = make_float2(0.f, 0.f);

    #pragma unroll
    for (int r = 0; r < NREL; r++) {
        int p = NREL + r;
        const int*   offp  = off  + (size_t)p * M;
        const int*   degp  = degi + (size_t)(p * 2 + 1) * M;
        const int*   adjp  = adj  + (size_t)p * E;
        const float* rsin  = degf + (size_t)(p * 2 + 1) * M;
        int st = __ldg(offp + w);
        int len = __ldg(degp + w);
        float2 acc = make_float2(0.f, 0.f);
        const __half* zr = z3 + (size_t)r * 64;

        for (int base = 0; base < len; base += 32) {
            int cnt = min(32, len - base);
            int myIdx = 0;
            if (lane < cnt) myIdx = __ldg(adjp + st + base + lane);
            int j = 0;
            for (; j + 4 <= cnt; j += 4) {
                int s0 = __shfl_sync(0xffffffffu, myIdx, j + 0);
                int s1 = __shfl_sync(0xffffffffu, myIdx, j + 1);
                int s2 = __shfl_sync(0xffffffffu, myIdx, j + 2);
                int s3 = __shfl_sync(0xffffffffu, myIdx, j + 3);
                uint32_t q0 = __ldg(reinterpret_cast<const uint32_t*>(zr + (size_t)s0 * 192 + lane * 2));
                uint32_t q1 = __ldg(reinterpret_cast<const uint32_t*>(zr + (size_t)s1 * 192 + lane * 2));
                uint32_t q2 = __ldg(reinterpret_cast<const uint32_t*>(zr + (size_t)s2 * 192 + lane * 2));
                uint32_t q3 = __ldg(reinterpret_cast<const uint32_t*>(zr + (size_t)s3 * 192 + lane * 2));
                float2 a0 = __half22float2(*reinterpret_cast<__half2*>(&q0));
                float2 a1 = __half22float2(*reinterpret_cast<__half2*>(&q1));
                float2 a2 = __half22float2(*reinterpret_cast<__half2*>(&q2));
                float2 a3 = __half22float2(*reinterpret_cast<__half2*>(&q3));
                acc.x += (a0.x + a1.x) + (a2.x + a3.x);
                acc.y += (a0.y + a1.y) + (a2.y + a3.y);
            }
            for (; j < cnt; j++) {
                int s0 = __shfl_sync(0xffffffffu, myIdx, j);
                uint32_t q0 = __ldg(reinterpret_cast<const uint32_t*>(zr + (size_t)s0 * 192 + lane * 2));
                float2 a0 = __half22float2(*reinterpret_cast<__half2*>(&q0));
                acc.x += a0.x; acc.y += a0.y;
            }
        }
        float ci = __ldg(rsin + w);
        tot.x += ci * acc.x; tot.y += ci * acc.y;
    }

    int col = lane * 2;
    tot.x += __ldg(b2 + col + 0) + __ldg(b2 + 64 + col + 0) + __ldg(b2 + 128 + col + 0);
    tot.y += __ldg(b2 + col + 1) + __ldg(b2 + 64 + col + 1) + __ldg(b2 + 128 + col + 1);
    *reinterpret_cast<float2*>(out + (size_t)w * 64 + col) = tot;
}

// ---------------- orchestration ----------------------------------------------
extern "C" void kernel_launch(void* const* d_in, const int* in_sizes, int n_in,
                              void* d_out, int out_size) {
    const float* x  = (const float*)d_in[0];
    const float* W1 = (const float*)d_in[1];
    const float* b1 = (const float*)d_in[2];
    const float* W2 = (const float*)d_in[3];
    const float* b2 = (const float*)d_in[4];
    const int*   ei = (const int*)d_in[5];
    float* out = (float*)d_out;

    const int M = in_sizes[0] / DIN;
    const int E = in_sizes[5] / (2 * NREL * 2);

    float* degf;
    __half* z3;
    __nv_bfloat16 *ahi, *alo, *w1hi, *w1lo, *w2hi, *w2lo;
    int *degi, *off, *cnt, *adj, *bsum;
    cudaGetSymbolAddress((void**)&z3,   g_z3);
    cudaGetSymbolAddress((void**)&ahi,  g_ahi);
    cudaGetSymbolAddress((void**)&alo,  g_alo);
    cudaGetSymbolAddress((void**)&w1hi, g_w1hi);
    cudaGetSymbolAddress((void**)&w1lo, g_w1lo);
    cudaGetSymbolAddress((void**)&w2hi, g_w2hi);
    cudaGetSymbolAddress((void**)&w2lo, g_w2lo);
    cudaGetSymbolAddress((void**)&degf, g_degf);
    cudaGetSymbolAddress((void**)&degi, g_degi);
    cudaGetSymbolAddress((void**)&off,  g_off);
    cudaGetSymbolAddress((void**)&cnt,  g_cnt);
    cudaGetSymbolAddress((void**)&adj,  g_adj);
    cudaGetSymbolAddress((void**)&bsum, g_bsum);

    const int TB = 256;
    auto blocks = [](long n, int tb) { return (int)((n + tb - 1) / tb); };
    const int nblk_scan = (M + SCAN_CHUNK - 1) / SCAN_CHUNK;
    const int gemm_grid = (M + 127) / 128;
    const int gw = blocks((long)M * 32, TB);

    const int SMEM_L1 = 128 * A_ST * 2 * 2 + 2 * 2 * 32 * (128 + 8) * 2;
    const int SMEM_L2 = 128 * A_ST * 2 * 2 + 2 * 2 * 32 * (64 + 8) * 2;
    cudaFuncSetAttribute(gemm_fused<128, false>,
                         cudaFuncAttributeMaxDynamicSharedMemorySize, SMEM_L1);
    cudaFuncSetAttribute(gemm_fused<64, true>,
                         cudaFuncAttributeMaxDynamicSharedMemorySize, SMEM_L2);

    // ---- fork side stream for CSR build ---------------------------------------
    cudaStream_t s2;
    cudaStreamCreateWithFlags(&s2, cudaStreamNonBlocking);
    cudaEvent_t evFork, evCsr1, evDeg2, evCsr2;
    cudaEventCreateWithFlags(&evFork, cudaEventDisableTiming);
    cudaEventCreateWithFlags(&evCsr1, cudaEventDisableTiming);
    cudaEventCreateWithFlags(&evDeg2, cudaEventDisableTiming);
    cudaEventCreateWithFlags(&evCsr2, cudaEventDisableTiming);
    cudaEventRecord(evFork, 0);
    cudaStreamWaitEvent(s2, evFork, 0);

    // ---- main: splits + fused layer-1 GEMM ------------------------------------
    split_kernel<<<blocks((long)M * DIN, TB), TB>>>(x, ahi, alo, M * DIN);
    split_kernel<<<blocks(NREL * DIN * DH, TB), TB>>>(W1, w1hi, w1lo, NREL * DIN * DH);
    split_kernel<<<blocks(NREL * DH * DOUT, TB), TB>>>(W2, w2hi, w2lo, NREL * DH * DOUT);
    gemm_fused<128, false><<<gemm_grid, 256, SMEM_L1>>>(
        ahi, alo, w1hi, w1lo, nullptr, z3, M);

    // ---- side: layer-1 CSR, then layer-2 CSR ----------------------------------
    cudaMemsetAsync(degi, 0, (size_t)12 * M * sizeof(int), s2);
    { dim3 g(blocks(E, TB), 3); count_deg_kernel<<<g, TB, 0, s2>>>(ei, degi, E, M, 0); }
    rsqrt_kernel<<<blocks((long)6 * M, TB), TB, 0, s2>>>(degi, degf, 6 * M);
    { dim3 g(nblk_scan, 3); scanA<<<g, 256, 0, s2>>>(degi, off, bsum, M, 0); }
    scanB<<<3, MAXBLK, 0, s2>>>(bsum, nblk_scan, 0);
    { dim3 g(blocks(M, TB), 3); scanC<<<g, TB, 0, s2>>>(off, cnt, bsum, M, 0); }
    { dim3 g(blocks(E, TB), 3); fill_adj_kernel<<<g, TB, 0, s2>>>(ei, cnt, adj, E, M, 0); }
    cudaEventRecord(evCsr1, s2);
    { dim3 g(blocks(E, TB), 3); count_deg_kernel<<<g, TB, 0, s2>>>(ei, degi, E, M, 3); }
    rsqrt_kernel<<<blocks((long)6 * M, TB), TB, 0, s2>>>(degi + (size_t)6 * M, degf + (size_t)6 * M, 6 * M);
    cudaEventRecord(evDeg2, s2);
    { dim3 g(nblk_scan, 3); scanA<<<g, 256, 0, s2>>>(degi, off, bsum, M, 3); }
    scanB<<<3, MAXBLK, 0, s2>>>(bsum, nblk_scan, 3);
    { dim3 g(blocks(M, TB), 3); scanC<<<g, TB, 0, s2>>>(off, cnt, bsum, M, 3); }
    { dim3 g(blocks(E, TB), 3); fill_adj_kernel<<<g, TB, 0, s2>>>(ei, cnt, adj, E, M, 3); }
    cudaEventRecord(evCsr2, s2);

    // ---- join: gatherL1 -> layer-2 GEMM -> gatherL2 ----------------------------
    cudaStreamWaitEvent(0, evCsr1, 0);
    gatherL1<<<gw, TB>>>(z3, ahi, alo, off, degi, adj, degf, b1, M, E);

    cudaStreamWaitEvent(0, evDeg2, 0);
    gemm_fused<64, true><<<gemm_grid, 256, SMEM_L2>>>(
        ahi, alo, w2hi, w2lo, degf + (size_t)6 * M, z3, M);

    cudaStreamWaitEvent(0, evCsr2, 0);
    gatherL2<<<gw, TB>>>(z3, out, off, degi, adj, degf, b2, M, E);

    cudaStreamDestroy(s2);
    cudaEventDestroy(evFork);
    cudaEventDestroy(evCsr1);
    cudaEventDestroy(evDeg2);
    cudaEventDestroy(evCsr2);
}

// round 17
// speedup vs baseline: 1.0296x; 1.0296x over previous
#include <cuda_runtime.h>
#include <cuda_bf16.h>
#include <cuda_fp16.h>
#include <cstdint>

// ---------------- problem constants ------------------------------------------
#define NMAX   100000
#define EMAX   1600000
#define DIN    128
#define DH     128
#define DOUT   64
#define NREL   3
#define NPAIR  6
#define SCAN_CHUNK 1024
#define MAXBLK 128

// ---------------- scratch (__device__ globals; no allocation allowed) --------
__device__ __align__(128) __half g_z3[(size_t)NMAX * (NREL * DIN)];
__device__ __align__(128) __nv_bfloat16 g_ahi[(size_t)NMAX * DIN];
__device__ __align__(128) __nv_bfloat16 g_alo[(size_t)NMAX * DIN];
__device__ __align__(128) __nv_bfloat16 g_w1hi[NREL * DIN * DH], g_w1lo[NREL * DIN * DH];
__device__ __align__(128) __nv_bfloat16 g_w2hi[NREL * DH * DOUT], g_w2lo[NREL * DH * DOUT];
__device__ int   g_degi[12 * NMAX];
__device__ float g_degf[12 * NMAX];
__device__ int   g_off [NPAIR * NMAX];
__device__ int   g_cnt [NPAIR * NMAX];
__device__ int   g_adj [(size_t)NPAIR * EMAX];
__device__ int   g_bsum[NPAIR * MAXBLK];

// ---------------- cp.async / mma helpers --------------------------------------
__device__ __forceinline__ void cpa16(void* smem, const void* g, bool valid) {
    uint32_t s = (uint32_t)__cvta_generic_to_shared(smem);
    int sz = valid ? 16 : 0;
    asm volatile("cp.async.cg.shared.global [%0], [%1], 16, %2;\n"
                 :: "r"(s), "l"(g), "r"(sz));
}
__device__ __forceinline__ void cpa_commit() {
    asm volatile("cp.async.commit_group;\n" ::: "memory");
}
__device__ __forceinline__ void cpa_wait0() {
    asm volatile("cp.async.wait_group 0;\n" ::: "memory");
}
__device__ __forceinline__ void ldsm_x4(uint32_t* r, uint32_t addr) {
    asm volatile("ldmatrix.sync.aligned.m8n8.x4.shared.b16 {%0,%1,%2,%3}, [%4];"
                 : "=r"(r[0]), "=r"(r[1]), "=r"(r[2]), "=r"(r[3]) : "r"(addr));
}
__device__ __forceinline__ void ldsm_x4t(uint32_t* r, uint32_t addr) {
    asm volatile("ldmatrix.sync.aligned.m8n8.x4.trans.shared.b16 {%0,%1,%2,%3}, [%4];"
                 : "=r"(r[0]), "=r"(r[1]), "=r"(r[2]), "=r"(r[3]) : "r"(addr));
}
__device__ __forceinline__ void mma16816(float* d, const uint32_t* a, const uint32_t* b) {
    asm volatile("mma.sync.aligned.m16n8k16.row.col.f32.bf16.bf16.f32 "
                 "{%0,%1,%2,%3},{%4,%5,%6,%7},{%8,%9},{%0,%1,%2,%3};"
                 : "+f"(d[0]), "+f"(d[1]), "+f"(d[2]), "+f"(d[3])
                 : "r"(a[0]), "r"(a[1]), "r"(a[2]), "r"(a[3]), "r"(b[0]), "r"(b[1]));
}

// ---------------- fp32 -> (bf16 hi, bf16 lo) split ---------------------------
__global__ void split_kernel(const float* __restrict__ src,
                             __nv_bfloat16* __restrict__ hi,
                             __nv_bfloat16* __restrict__ lo, int n) {
    int i = blockIdx.x * blockDim.x + threadIdx.x;
    if (i >= n) return;
    float v = __ldg(src + i);
    __nv_bfloat16 h = __float2bfloat16(v);
    hi[i] = h;
    lo[i] = __float2bfloat16(v - __bfloat162float(h));
}

// ---------------- degree counting ---------------------------------------------
__global__ void count_deg_kernel(const int* __restrict__ ei, int* __restrict__ degi,
                                 int E, int M, int pbase) {
    int p = pbase + blockIdx.y;
    int e = blockIdx.x * blockDim.x + threadIdx.x;
    if (e >= E) return;
    int s = __ldg(ei + (size_t)(p * 2 + 0) * E + e);
    int d = __ldg(ei + (size_t)(p * 2 + 1) * E + e);
    atomicAdd(degi + (size_t)(p * 2 + 0) * M + s, 1);
    atomicAdd(degi + (size_t)(p * 2 + 1) * M + d, 1);
}

__global__ void rsqrt_kernel(const int* __restrict__ degi, float* __restrict__ degf, int n) {
    int i = blockIdx.x * blockDim.x + threadIdx.x;
    if (i < n) degf[i] = rsqrtf((float)max(degi[i], 1));
}

// ---------------- exclusive scan -> CSR offsets -------------------------------
__global__ __launch_bounds__(256)
void scanA(const int* __restrict__ degi, int* __restrict__ off,
           int* __restrict__ bsum, int M, int pbase) {
    int p = pbase + blockIdx.y;
    const int* deg = degi + (size_t)(p * 2 + 1) * M;
    int* o = off + (size_t)p * M;
    int base = blockIdx.x * SCAN_CHUNK;
    int tid = threadIdx.x;

    int v[4];
    int t = 0;
    #pragma unroll
    for (int k = 0; k < 4; k++) {
        int idx = base + tid * 4 + k;
        v[k] = (idx < M) ? deg[idx] : 0;
        t += v[k];
    }
    __shared__ int sm[256];
    sm[tid] = t;
    __syncthreads();
    #pragma unroll
    for (int ofs = 1; ofs < 256; ofs <<= 1) {
        int u = (tid >= ofs) ? sm[tid - ofs] : 0;
        __syncthreads();
        sm[tid] += u;
        __syncthreads();
    }
    int run = sm[tid] - t;
    #pragma unroll
    for (int k = 0; k < 4; k++) {
        int idx = base + tid * 4 + k;
        if (idx < M) o[idx] = run;
        run += v[k];
    }
    if (tid == 255) bsum[p * MAXBLK + blockIdx.x] = sm[255];
}

__global__ __launch_bounds__(MAXBLK)
void scanB(int* __restrict__ bsum, int nblk, int pbase) {
    int p = pbase + blockIdx.x;
    int tid = threadIdx.x;
    int* b = bsum + p * MAXBLK;
    int t = (tid < nblk) ? b[tid] : 0;
    __shared__ int sm[MAXBLK];
    sm[tid] = t;
    __syncthreads();
    #pragma unroll
    for (int ofs = 1; ofs < MAXBLK; ofs <<= 1) {
        int u = (tid >= ofs) ? sm[tid - ofs] : 0;
        __syncthreads();
        sm[tid] += u;
        __syncthreads();
    }
    if (tid < nblk) b[tid] = sm[tid] - t;
}

__global__ void scanC(int* __restrict__ off, int* __restrict__ cnt,
                      const int* __restrict__ bsum, int M, int pbase) {
    int p = pbase + blockIdx.y;
    int i = blockIdx.x * blockDim.x + threadIdx.x;
    if (i < M) {
        int v = off[(size_t)p * M + i] + bsum[p * MAXBLK + (i >> 10)];
        off[(size_t)p * M + i] = v;
        cnt[(size_t)p * M + i] = v;
    }
}

__global__ void fill_adj_kernel(const int* __restrict__ ei,
                                int* __restrict__ cnt, int* __restrict__ adj,
                                int E, int M, int pbase) {
    int p = pbase + blockIdx.y;
    int e = blockIdx.x * blockDim.x + threadIdx.x;
    if (e >= E) return;
    int s = __ldg(ei + (size_t)(p * 2 + 0) * E + e);
    int d = __ldg(ei + (size_t)(p * 2 + 1) * E + e);
    int pos = atomicAdd(cnt + (size_t)p * M + d, 1);
    adj[(size_t)p * E + pos] = s;
}

// ---------------- relation-fused mma.sync GEMM, register epilogue -------------
#define A_ST 136

template<int BN, bool SCALE>
__global__ __launch_bounds__(256, 2)
void gemm_fused(const __nv_bfloat16* __restrict__ Ahi,
                const __nv_bfloat16* __restrict__ Alo,
                const __nv_bfloat16* __restrict__ Bhi,
                const __nv_bfloat16* __restrict__ Blo,
                const float* __restrict__ rsbase,
                __half* __restrict__ C, int M) {
    constexpr int LDC = NREL * BN;
    constexpr int BST = BN + 8;
    constexpr int KCH = 4;
    constexpr int TOT = NREL * KCH;
    constexpr int BXF = 32 * BN / 8;
    constexpr int WNT = BN / 2 / 8;

    extern __shared__ __align__(16) char dsm[];
    __nv_bfloat16* sAhi = reinterpret_cast<__nv_bfloat16*>(dsm);
    __nv_bfloat16* sAlo = sAhi + 128 * A_ST;
    __nv_bfloat16* sB   = sAlo + 128 * A_ST;

    const int tid  = threadIdx.x;
    const int w    = tid >> 5;
    const int lane = tid & 31;
    const int warp_row = w & 3;
    const int warp_col = w >> 2;
    const int m_off = warp_row * 32;
    const int n_off = warp_col * (BN / 2);
    const int row0 = blockIdx.x * 128;

    const uint32_t saHi = (uint32_t)__cvta_generic_to_shared(sAhi);
    const uint32_t saLo = (uint32_t)__cvta_generic_to_shared(sAlo);
    const uint32_t sb0  = (uint32_t)__cvta_generic_to_shared(sB);

    #pragma unroll
    for (int i = 0; i < 8; i++) {
        int slot = tid + i * 256;
        int r = slot >> 4;
        int c = (slot & 15) * 8;
        int gr = row0 + r;
        bool valid = gr < M;
        const __nv_bfloat16* gh = Ahi + (size_t)gr * 128 + c;
        const __nv_bfloat16* gl = Alo + (size_t)gr * 128 + c;
        cpa16(sAhi + r * A_ST + c, valid ? gh : (const void*)Ahi, valid);
        cpa16(sAlo + r * A_ST + c, valid ? gl : (const void*)Alo, valid);
    }

    auto loadB = [&](int it, int st) {
        int rel = it / KCH;
        int kc = (it % KCH) * 32;
        __nv_bfloat16* dh = sB + st * 2 * 32 * BST;
        __nv_bfloat16* dl = dh + 32 * BST;
        const __nv_bfloat16* gh = Bhi + (size_t)rel * 128 * BN;
        const __nv_bfloat16* gl = Blo + (size_t)rel * 128 * BN;
        #pragma unroll
        for (int i = 0; i < BXF / 256; i++) {
            int slot = tid + i * 256;
            int r = slot / (BN / 8);
            int c = (slot % (BN / 8)) * 8;
            cpa16(dh + r * BST + c, gh + (size_t)(kc + r) * BN + c, true);
            cpa16(dl + r * BST + c, gl + (size_t)(kc + r) * BN + c, true);
        }
    };
    loadB(0, 0);
    cpa_commit();

    float acc[2][WNT][4];
    #pragma unroll
    for (int mt = 0; mt < 2; mt++)
        #pragma unroll
        for (int nt = 0; nt < WNT; nt++)
            #pragma unroll
            for (int k = 0; k < 4; k++) acc[mt][nt][k] = 0.0f;

    const int aRow = (lane & 15);
    const int aCol = (lane >> 4) * 8;
    const int bRow = (lane & 7) + ((lane >> 3) & 1) * 8;
    const int bCol = (lane >> 4) * 8;

    for (int it = 0; it < TOT; it++) {
        cpa_wait0();
        __syncthreads();
        if (it + 1 < TOT) { loadB(it + 1, (it + 1) & 1); cpa_commit(); }

        const uint32_t sbh = sb0 + (uint32_t)((it & 1) * 2 * 32 * BST) * 2;
        const uint32_t sbl = sbh + 32 * BST * 2;
        const int kc = (it % KCH) * 32;

        #pragma unroll
        for (int ks = 0; ks < 32; ks += 16) {
            const int kpos = kc + ks;
            uint32_t bhi[WNT][2], blo[WNT][2];
            #pragma unroll
            for (int g = 0; g < WNT / 2; g++) {
                uint32_t t[4];
                uint32_t boff = (uint32_t)((ks + bRow) * BST + n_off + g * 16 + bCol) * 2;
                ldsm_x4t(t, sbh + boff);
                bhi[2 * g][0] = t[0]; bhi[2 * g][1] = t[1];
                bhi[2 * g + 1][0] = t[2]; bhi[2 * g + 1][1] = t[3];
                ldsm_x4t(t, sbl + boff);
                blo[2 * g][0] = t[0]; blo[2 * g][1] = t[1];
                blo[2 * g + 1][0] = t[2]; blo[2 * g + 1][1] = t[3];
            }
            #pragma unroll
            for (int mt = 0; mt < 2; mt++) {
                uint32_t ahi[4], alo[4];
                uint32_t aoff = (uint32_t)((m_off + mt * 16 + aRow) * A_ST + kpos + aCol) * 2;
                ldsm_x4(ahi, saHi + aoff);
                ldsm_x4(alo, saLo + aoff);
                #pragma unroll
                for (int nt = 0; nt < WNT; nt++) {
                    mma16816(acc[mt][nt], ahi, bhi[nt]);
                    mma16816(acc[mt][nt], ahi, blo[nt]);
                    mma16816(acc[mt][nt], alo, bhi[nt]);
                }
            }
        }

        if ((it % KCH) == KCH - 1) {
            int rel = it / KCH;
            const float* rs = rsbase + (size_t)rel * 2 * M;
            #pragma unroll
            for (int mt = 0; mt < 2; mt++) {
                int r0 = row0 + m_off + mt * 16 + (lane >> 2);
                int r1 = r0 + 8;
                float s0 = 1.0f, s1 = 1.0f;
                if (SCALE) {
                    if (r0 < M) s0 = __ldg(rs + r0);
                    if (r1 < M) s1 = __ldg(rs + r1);
                }
                #pragma unroll
                for (int nt = 0; nt < WNT; nt++) {
                    int c = rel * BN + n_off + nt * 8 + (lane & 3) * 2;
                    if (r0 < M) {
                        __half2 p = __floats2half2_rn(acc[mt][nt][0] * s0, acc[mt][nt][1] * s0);
                        *reinterpret_cast<uint32_t*>(C + (size_t)r0 * LDC + c) =
                            *reinterpret_cast<uint32_t*>(&p);
                    }
                    if (r1 < M) {
                        __half2 p = __floats2half2_rn(acc[mt][nt][2] * s1, acc[mt][nt][3] * s1);
                        *reinterpret_cast<uint32_t*>(C + (size_t)r1 * LDC + c) =
                            *reinterpret_cast<uint32_t*>(&p);
                    }
                    #pragma unroll
                    for (int k = 0; k < 4; k++) acc[mt][nt][k] = 0.0f;
                }
            }
        }
    }
}

// ---------------- fused 3-relation gathers (z pre-scaled by rs_out) -----------
__global__ __launch_bounds__(256)
void gatherL1(const __half* __restrict__ z3,
              __nv_bfloat16* __restrict__ ahi, __nv_bfloat16* __restrict__ alo,
              const int* __restrict__ off, const int* __restrict__ degi,
              const int* __restrict__ adj, const float* __restrict__ degf,
              const float* __restrict__ b1, int M, int E) {
    int w = (blockIdx.x * blockDim.x + threadIdx.x) >> 5;
    if (w >= M) return;
    int lane = threadIdx.x & 31;
    float4 tot = make_float4(0.f, 0.f, 0.f, 0.f);

    #pragma unroll
    for (int r = 0; r < NREL; r++) {
        const int*   offp  = off  + (size_t)r * M;
        const int*   degp  = degi + (size_t)(r * 2 + 1) * M;
        const int*   adjp  = adj  + (size_t)r * E;
        const float* rsin  = degf + (size_t)(r * 2 + 1) * M;
        int st = __ldg(offp + w);
        int len = __ldg(degp + w);
        float4 acc = make_float4(0.f, 0.f, 0.f, 0.f);
        const __half* zr = z3 + (size_t)r * 128;

        for (int base = 0; base < len; base += 32) {
            int cnt = min(32, len - base);
            int myIdx = 0;
            if (lane < cnt) myIdx = __ldg(adjp + st + base + lane);
            int j = 0;
            for (; j + 4 <= cnt; j += 4) {
                int s0 = __shfl_sync(0xffffffffu, myIdx, j + 0);
                int s1 = __shfl_sync(0xffffffffu, myIdx, j + 1);
                int s2 = __shfl_sync(0xffffffffu, myIdx, j + 2);
                int s3 = __shfl_sync(0xffffffffu, myIdx, j + 3);
                uint2 q0 = __ldg(reinterpret_cast<const uint2*>(zr + (size_t)s0 * 384 + lane * 4));
                uint2 q1 = __ldg(reinterpret_cast<const uint2*>(zr + (size_t)s1 * 384 + lane * 4));
                uint2 q2 = __ldg(reinterpret_cast<const uint2*>(zr + (size_t)s2 * 384 + lane * 4));
                uint2 q3 = __ldg(reinterpret_cast<const uint2*>(zr + (size_t)s3 * 384 + lane * 4));
                float2 a0 = __half22float2(*reinterpret_cast<__half2*>(&q0.x));
                float2 b0 = __half22float2(*reinterpret_cast<__half2*>(&q0.y));
                float2 a1 = __half22float2(*reinterpret_cast<__half2*>(&q1.x));
                float2 b1v = __half22float2(*reinterpret_cast<__half2*>(&q1.y));
                float2 a2 = __half22float2(*reinterpret_cast<__half2*>(&q2.x));
                float2 b2v = __half22float2(*reinterpret_cast<__half2*>(&q2.y));
                float2 a3 = __half22float2(*reinterpret_cast<__half2*>(&q3.x));
                float2 b3v = __half22float2(*reinterpret_cast<__half2*>(&q3.y));
                acc.x += (a0.x + a1.x) + (a2.x + a3.x);
                acc.y += (a0.y + a1.y) + (a2.y + a3.y);
                acc.z += (b0.x + b1v.x) + (b2v.x + b3v.x);
                acc.w += (b0.y + b1v.y) + (b2v.y + b3v.y);
            }
            for (; j < cnt; j++) {
                int s0 = __shfl_sync(0xffffffffu, myIdx, j);
                uint2 q0 = __ldg(reinterpret_cast<const uint2*>(zr + (size_t)s0 * 384 + lane * 4));
                float2 a0 = __half22float2(*reinterpret_cast<__half2*>(&q0.x));
                float2 b0 = __half22float2(*reinterpret_cast<__half2*>(&q0.y));
                acc.x += a0.x; acc.y += a0.y;
                acc.z += b0.x; acc.w += b0.y;
            }
        }
        float ci = __ldg(rsin + w);
        tot.x += ci * acc.x; tot.y += ci * acc.y;
        tot.z += ci * acc.z; tot.w += ci * acc.w;
    }

    int col = lane * 4;
    tot.x = fmaxf(tot.x + __ldg(b1 + col + 0) + __ldg(b1 + 128 + col + 0) + __ldg(b1 + 256 + col + 0), 0.f);
    tot.y = fmaxf(tot.y + __ldg(b1 + col + 1) + __ldg(b1 + 128 + col + 1) + __ldg(b1 + 256 + col + 1), 0.f);
    tot.z = fmaxf(tot.z + __ldg(b1 + col + 2) + __ldg(b1 + 128 + col + 2) + __ldg(b1 + 256 + col + 2), 0.f);
    tot.w = fmaxf(tot.w + __ldg(b1 + col + 3) + __ldg(b1 + 128 + col + 3) + __ldg(b1 + 256 + col + 3), 0.f);

    __nv_bfloat16 hx = __float2bfloat16(tot.x), hy = __float2bfloat16(tot.y);
    __nv_bfloat16 hz = __float2bfloat16(tot.z), hw = __float2bfloat16(tot.w);
    __nv_bfloat16 lx = __float2bfloat16(tot.x - __bfloat162float(hx));
    __nv_bfloat16 ly = __float2bfloat16(tot.y - __bfloat162float(hy));
    __nv_bfloat16 lz = __float2bfloat16(tot.z - __bfloat162float(hz));
    __nv_bfloat16 lw = __float2bfloat16(tot.w - __bfloat162float(hw));
    __nv_bfloat162 h0 = __nv_bfloat162(hx, hy), h1 = __nv_bfloat162(hz, hw);
    __nv_bfloat162 l0 = __nv_bfloat162(lx, ly), l1 = __nv_bfloat162(lz, lw);
    uint2 oh, ol;
    oh.x = *reinterpret_cast<uint32_t*>(&h0); oh.y = *reinterpret_cast<uint32_t*>(&h1);
    ol.x = *reinterpret_cast<uint32_t*>(&l0); ol.y = *reinterpret_cast<uint32_t*>(&l1);
    *reinterpret_cast<uint2*>(ahi + (size_t)w * 128 + col) = oh;
    *reinterpret_cast<uint2*>(alo + (size_t)w * 128 + col) = ol;
}

__global__ __launch_bounds__(256)
void gatherL2(const __half* __restrict__ z3, float* __restrict__ out,
              const int* __restrict__ off, const int* __restrict__ degi,
              const int* __restrict__ adj, const float* __restrict__ degf,
              const float* __restrict__ b2, int M, int E) {
    int w = (blockIdx.x * blockDim.x + threadIdx.x) >> 5;
    if (w >= M) return;
    int lane = threadIdx.x & 31;
    float2 tot = make_float2(0.f, 0.f);

    #pragma unroll
    for (int r = 0; r < NREL; r++) {
        int p = NREL + r;
        const int*   offp  = off  + (size_t)p * M;
        const int*   degp  = degi + (size_t)(p * 2 + 1) * M;
        const int*   adjp  = adj  + (size_t)p * E;
        const float* rsin  = degf + (size_t)(p * 2 + 1) * M;
        int st = __ldg(offp + w);
        int len = __ldg(degp + w);
        float2 acc = make_float2(0.f, 0.f);
        const __half* zr = z3 + (size_t)r * 64;

        for (int base = 0; base < len; base += 32) {
            int cnt = min(32, len - base);
            int myIdx = 0;
            if (lane < cnt) myIdx = __ldg(adjp + st + base + lane);
            int j = 0;
            for (; j + 4 <= cnt; j += 4) {
                int s0 = __shfl_sync(0xffffffffu, myIdx, j + 0);
                int s1 = __shfl_sync(0xffffffffu, myIdx, j + 1);
                int s2 = __shfl_sync(0xffffffffu, myIdx, j + 2);
                int s3 = __shfl_sync(0xffffffffu, myIdx, j + 3);
                uint32_t q0 = __ldg(reinterpret_cast<const uint32_t*>(zr + (size_t)s0 * 192 + lane * 2));
                uint32_t q1 = __ldg(reinterpret_cast<const uint32_t*>(zr + (size_t)s1 * 192 + lane * 2));
                uint32_t q2 = __ldg(reinterpret_cast<const uint32_t*>(zr + (size_t)s2 * 192 + lane * 2));
                uint32_t q3 = __ldg(reinterpret_cast<const uint32_t*>(zr + (size_t)s3 * 192 + lane * 2));
                float2 a0 = __half22float2(*reinterpret_cast<__half2*>(&q0));
                float2 a1 = __half22float2(*reinterpret_cast<__half2*>(&q1));
                float2 a2 = __half22float2(*reinterpret_cast<__half2*>(&q2));
                float2 a3 = __half22float2(*reinterpret_cast<__half2*>(&q3));
                acc.x += (a0.x + a1.x) + (a2.x + a3.x);
                acc.y += (a0.y + a1.y) + (a2.y + a3.y);
            }
            for (; j < cnt; j++) {
                int s0 = __shfl_sync(0xffffffffu, myIdx, j);
                uint32_t q0 = __ldg(reinterpret_cast<const uint32_t*>(zr + (size_t)s0 * 192 + lane * 2));
                float2 a0 = __half22float2(*reinterpret_cast<__half2*>(&q0));
                acc.x += a0.x; acc.y += a0.y;
            }
        }
        float ci = __ldg(rsin + w);
        tot.x += ci * acc.x; tot.y += ci * acc.y;
    }

    int col = lane * 2;
    tot.x += __ldg(b2 + col + 0) + __ldg(b2 + 64 + col + 0) + __ldg(b2 + 128 + col + 0);
    tot.y += __ldg(b2 + col + 1) + __ldg(b2 + 64 + col + 1) + __ldg(b2 + 128 + col + 1);
    *reinterpret_cast<float2*>(out + (size_t)w * 64 + col) = tot;
}

// ---------------- orchestration ----------------------------------------------
extern "C" void kernel_launch(void* const* d_in, const int* in_sizes, int n_in,
                              void* d_out, int out_size) {
    const float* x  = (const float*)d_in[0];
    const float* W1 = (const float*)d_in[1];
    const float* b1 = (const float*)d_in[2];
    const float* W2 = (const float*)d_in[3];
    const float* b2 = (const float*)d_in[4];
    const int*   ei = (const int*)d_in[5];
    float* out = (float*)d_out;

    const int M = in_sizes[0] / DIN;
    const int E = in_sizes[5] / (2 * NREL * 2);

    float* degf;
    __half* z3;
    __nv_bfloat16 *ahi, *alo, *w1hi, *w1lo, *w2hi, *w2lo;
    int *degi, *off, *cnt, *adj, *bsum;
    cudaGetSymbolAddress((void**)&z3,   g_z3);
    cudaGetSymbolAddress((void**)&ahi,  g_ahi);
    cudaGetSymbolAddress((void**)&alo,  g_alo);
    cudaGetSymbolAddress((void**)&w1hi, g_w1hi);
    cudaGetSymbolAddress((void**)&w1lo, g_w1lo);
    cudaGetSymbolAddress((void**)&w2hi, g_w2hi);
    cudaGetSymbolAddress((void**)&w2lo, g_w2lo);
    cudaGetSymbolAddress((void**)&degf, g_degf);
    cudaGetSymbolAddress((void**)&degi, g_degi);
    cudaGetSymbolAddress((void**)&off,  g_off);
    cudaGetSymbolAddress((void**)&cnt,  g_cnt);
    cudaGetSymbolAddress((void**)&adj,  g_adj);
    cudaGetSymbolAddress((void**)&bsum, g_bsum);

    const int TB = 256;
    auto blocks = [](long n, int tb) { return (int)((n + tb - 1) / tb); };
    const int nblk_scan = (M + SCAN_CHUNK - 1) / SCAN_CHUNK;
    const int gemm_grid = (M + 127) / 128;
    const int gw = blocks((long)M * 32, TB);

    const int SMEM_L1 = 128 * A_ST * 2 * 2 + 2 * 2 * 32 * (128 + 8) * 2;
    const int SMEM_L2 = 128 * A_ST * 2 * 2 + 2 * 2 * 32 * (64 + 8) * 2;
    cudaFuncSetAttribute(gemm_fused<128, true>,
                         cudaFuncAttributeMaxDynamicSharedMemorySize, SMEM_L1);
    cudaFuncSetAttribute(gemm_fused<64, true>,
                         cudaFuncAttributeMaxDynamicSharedMemorySize, SMEM_L2);

    // ---- fork side stream for degree/CSR build ---------------------------------
    cudaStream_t s2;
    cudaStreamCreateWithFlags(&s2, cudaStreamNonBlocking);
    cudaEvent_t evFork, evDeg1, evCsr1, evDeg2, evCsr2;
    cudaEventCreateWithFlags(&evFork, cudaEventDisableTiming);
    cudaEventCreateWithFlags(&evDeg1, cudaEventDisableTiming);
    cudaEventCreateWithFlags(&evCsr1, cudaEventDisableTiming);
    cudaEventCreateWithFlags(&evDeg2, cudaEventDisableTiming);
    cudaEventCreateWithFlags(&evCsr2, cudaEventDisableTiming);
    cudaEventRecord(evFork, 0);
    cudaStreamWaitEvent(s2, evFork, 0);

    // ---- side: layer-1 degrees first (gates GEMM1 scale), then CSR1, then L2 ---
    cudaMemsetAsync(degi, 0, (size_t)12 * M * sizeof(int), s2);
    { dim3 g(blocks(E, TB), 3); count_deg_kernel<<<g, TB, 0, s2>>>(ei, degi, E, M, 0); }
    rsqrt_kernel<<<blocks((long)6 * M, TB), TB, 0, s2>>>(degi, degf, 6 * M);
    cudaEventRecord(evDeg1, s2);
    { dim3 g(nblk_scan, 3); scanA<<<g, 256, 0, s2>>>(degi, off, bsum, M, 0); }
    scanB<<<3, MAXBLK, 0, s2>>>(bsum, nblk_scan, 0);
    { dim3 g(blocks(M, TB), 3); scanC<<<g, TB, 0, s2>>>(off, cnt, bsum, M, 0); }
    { dim3 g(blocks(E, TB), 3); fill_adj_kernel<<<g, TB, 0, s2>>>(ei, cnt, adj, E, M, 0); }
    cudaEventRecord(evCsr1, s2);
    { dim3 g(blocks(E, TB), 3); count_deg_kernel<<<g, TB, 0, s2>>>(ei, degi, E, M, 3); }
    rsqrt_kernel<<<blocks((long)6 * M, TB), TB, 0, s2>>>(degi + (size_t)6 * M, degf + (size_t)6 * M, 6 * M);
    cudaEventRecord(evDeg2, s2);
    { dim3 g(nblk_scan, 3); scanA<<<g, 256, 0, s2>>>(degi, off, bsum, M, 3); }
    scanB<<<3, MAXBLK, 0, s2>>>(bsum, nblk_scan, 3);
    { dim3 g(blocks(M, TB), 3); scanC<<<g, TB, 0, s2>>>(off, cnt, bsum, M, 3); }
    { dim3 g(blocks(E, TB), 3); fill_adj_kernel<<<g, TB, 0, s2>>>(ei, cnt, adj, E, M, 3); }
    cudaEventRecord(evCsr2, s2);

    // ---- main: splits for GEMM1, wait degrees, GEMM1 with fused rs_out ---------
    split_kernel<<<blocks((long)M * DIN, TB), TB>>>(x, ahi, alo, M * DIN);
    split_kernel<<<blocks(NREL * DIN * DH, TB), TB>>>(W1, w1hi, w1lo, NREL * DIN * DH);
    cudaStreamWaitEvent(0, evDeg1, 0);
    gemm_fused<128, true><<<gemm_grid, 256, SMEM_L1>>>(
        ahi, alo, w1hi, w1lo, degf, z3, M);
    // W2 split off the critical path (needed only by GEMM2)
    split_kernel<<<blocks(NREL * DH * DOUT, TB), TB>>>(W2, w2hi, w2lo, NREL * DH * DOUT);

    // ---- join: gatherL1 -> layer-2 GEMM -> gatherL2 ----------------------------
    cudaStreamWaitEvent(0, evCsr1, 0);
    gatherL1<<<gw, TB>>>(z3, ahi, alo, off, degi, adj, degf, b1, M, E);

    cudaStreamWaitEvent(0, evDeg2, 0);
    gemm_fused<64, true><<<gemm_grid, 256, SMEM_L2>>>(
        ahi, alo, w2hi, w2lo, degf + (size_t)6 * M, z3, M);

    cudaStreamWaitEvent(0, evCsr2, 0);
    gatherL2<<<gw, TB>>>(z3, out, off, degi, adj, degf, b2, M, E);

    cudaStreamDestroy(s2);
    cudaEventDestroy(evFork);
    cudaEventDestroy(evDeg1);
    cudaEventDestroy(evCsr1);
    cudaEventDestroy(evDeg2);
    cudaEventDestroy(evCsr2);
}